// round 11
// baseline (speedup 1.0000x reference)
#include <cuda_runtime.h>
#include <cstdint>
#include <math.h>

#define BB 4
#define TT 1024
#define DMODEL 512
#define HH 8
#define NEG_INF_F (-1000000000.0f)

// ---------------- scratch (device globals; no allocation) ----------------
__device__ float g_q[BB*TT*DMODEL];
__device__ float g_k[BB*TT*DMODEL];
__device__ float g_v[BB*TT*DMODEL];
__device__ float g_res[BB*TT*DMODEL];
__device__ float g_maskv[HH*DMODEL];
__device__ float g_m2[HH*DMODEL];
__device__ float g_inv_scale[HH];
__device__ int   g_dlo[HH];
__device__ int   g_dhi[HH];
__device__ float g_ctx[BB*TT*DMODEL];

// ================= mma.sync tf32 machinery =================
__device__ __forceinline__ float tf32_rna(float x) {
    float r; asm("cvt.rna.tf32.f32 %0, %1;" : "=f"(r) : "f"(x)); return r;
}
__device__ __forceinline__ float2 split_tf32(float x) {
    float h = tf32_rna(x);
    return make_float2(h, x - h);
}
__device__ __forceinline__ void mma8(float c[4], const uint32_t a[4], uint32_t b0, uint32_t b1) {
    asm volatile(
        "mma.sync.aligned.m16n8k8.row.col.f32.tf32.tf32.f32 "
        "{%0,%1,%2,%3}, {%4,%5,%6,%7}, {%8,%9}, {%0,%1,%2,%3};"
        : "+f"(c[0]), "+f"(c[1]), "+f"(c[2]), "+f"(c[3])
        : "r"(a[0]), "r"(a[1]), "r"(a[2]), "r"(a[3]), "r"(b0), "r"(b1));
}

#define PAD 133    // float2 per k-row
#define PADH 136   // float per s-row for P tile

// A fill: src row-major [m][k] (ld) -> As[k][m] split  (128 x 16)
__device__ __forceinline__ void fillA_plain(const float* __restrict__ src, int ld, int m0, int k0,
                                            float2 (*As)[PAD], int tid) {
    #pragma unroll
    for (int it = 0; it < 2; it++) {
        int idx = it*256 + tid;
        int m = idx >> 2, k4 = (idx & 3) << 2;
        float4 v = *(const float4*)(src + (size_t)(m0+m)*ld + k0 + k4);
        As[k4+0][m] = split_tf32(v.x);
        As[k4+1][m] = split_tf32(v.y);
        As[k4+2][m] = split_tf32(v.z);
        As[k4+3][m] = split_tf32(v.w);
    }
}
// A fill with per-k scale (Q * m2)
__device__ __forceinline__ void fillA_scaled(const float* __restrict__ src, int ld, int m0, int k0,
                                             const float* __restrict__ scl,
                                             float2 (*As)[PAD], int tid) {
    #pragma unroll
    for (int it = 0; it < 2; it++) {
        int idx = it*256 + tid;
        int m = idx >> 2, k4 = (idx & 3) << 2;
        float4 v = *(const float4*)(src + (size_t)(m0+m)*ld + k0 + k4);
        float4 s = *(const float4*)(scl + k0 + k4);
        As[k4+0][m] = split_tf32(v.x * s.x);
        As[k4+1][m] = split_tf32(v.y * s.y);
        As[k4+2][m] = split_tf32(v.z * s.z);
        As[k4+3][m] = split_tf32(v.w * s.w);
    }
}
// B fill along n: src row-major [k][n] (ld) -> Bs[k][n]  (16 x 128)
__device__ __forceinline__ void fillB_n(const float* __restrict__ src, int ld, int k0, int n0,
                                        float2 (*Bs)[PAD], int tid) {
    #pragma unroll
    for (int it = 0; it < 2; it++) {
        int idx = it*256 + tid;
        int k = idx >> 5, n4 = (idx & 31) << 2;
        float4 v = *(const float4*)(src + (size_t)(k0+k)*ld + n0 + n4);
        Bs[k][n4+0] = split_tf32(v.x);
        Bs[k][n4+1] = split_tf32(v.y);
        Bs[k][n4+2] = split_tf32(v.z);
        Bs[k][n4+3] = split_tf32(v.w);
    }
}
// guarded V fill (zero-fill cols >= DMODEL)
__device__ __forceinline__ void fillB_nV(const float* __restrict__ src, int k0, int n0,
                                         float2 (*Bs)[PAD], int tid) {
    #pragma unroll
    for (int it = 0; it < 2; it++) {
        int idx = it*256 + tid;
        int k = idx >> 5, n4 = (idx & 31) << 2;
        float4 v = make_float4(0.f,0.f,0.f,0.f);
        if (n0 + n4 + 3 < DMODEL)
            v = *(const float4*)(src + (size_t)(k0+k)*DMODEL + n0 + n4);
        Bs[k][n4+0] = split_tf32(v.x);
        Bs[k][n4+1] = split_tf32(v.y);
        Bs[k][n4+2] = split_tf32(v.z);
        Bs[k][n4+3] = split_tf32(v.w);
    }
}
// K fill for flash: 32 rows x 16 k -> Bs[k][n]
__device__ __forceinline__ void fillB_k32(const float* __restrict__ src, int k0, int n0,
                                          float2 (*Bs)[PAD], int tid) {
    int n = tid >> 3, k2 = (tid & 7) << 1;
    float2 v = *(const float2*)(src + (size_t)(n0+n)*DMODEL + k0 + k2);
    Bs[k2+0][n] = split_tf32(v.x);
    Bs[k2+1][n] = split_tf32(v.y);
}

// 3-term stage (qkv/out): 4m x 2n warp layout
__device__ __forceinline__ void warp_mma_stage(const float2 (*As)[PAD], const float2 (*Bs)[PAD],
                                               int mrow, int ncol, int kq, float c[2][8][4]) {
    #pragma unroll
    for (int k8o = 0; k8o < 16; k8o += 8) {
        uint32_t ah[2][4], al[2][4];
        #pragma unroll
        for (int mt = 0; mt < 2; mt++) {
            float2 x0 = As[k8o+kq  ][mrow + mt*16];
            float2 x1 = As[k8o+kq  ][mrow + mt*16 + 8];
            float2 x2 = As[k8o+4+kq][mrow + mt*16];
            float2 x3 = As[k8o+4+kq][mrow + mt*16 + 8];
            ah[mt][0] = __float_as_uint(x0.x); al[mt][0] = __float_as_uint(x0.y);
            ah[mt][1] = __float_as_uint(x1.x); al[mt][1] = __float_as_uint(x1.y);
            ah[mt][2] = __float_as_uint(x2.x); al[mt][2] = __float_as_uint(x2.y);
            ah[mt][3] = __float_as_uint(x3.x); al[mt][3] = __float_as_uint(x3.y);
        }
        #pragma unroll
        for (int nt = 0; nt < 8; nt++) {
            float2 y0 = Bs[k8o+kq  ][ncol + nt*8];
            float2 y1 = Bs[k8o+4+kq][ncol + nt*8];
            uint32_t bh0 = __float_as_uint(y0.x), bl0 = __float_as_uint(y0.y);
            uint32_t bh1 = __float_as_uint(y1.x), bl1 = __float_as_uint(y1.y);
            #pragma unroll
            for (int mt = 0; mt < 2; mt++) {
                mma8(c[mt][nt], ah[mt], bh0, bh1);
                mma8(c[mt][nt], ah[mt], bl0, bl1);
                mma8(c[mt][nt], al[mt], bh0, bh1);
            }
        }
    }
}

// ---------------- K2: QKV projection (4096x1536x512) ----------------
__global__ __launch_bounds__(256) void mma_qkv(const float* __restrict__ A,
                                               const float* __restrict__ B,
                                               const float* __restrict__ bias) {
    __shared__ float2 As[16][PAD], Bs[16][PAD];
    int tid = threadIdx.x, lane = tid & 31, wid = tid >> 5;
    int wm = wid >> 1, wn = wid & 1;
    int m0 = blockIdx.y * 128, n0 = blockIdx.x * 128;
    int mrow = wm*32 + (lane>>2), ncol = wn*64 + (lane>>2), kq = lane & 3;
    float c[2][8][4] = {};
    for (int k0 = 0; k0 < DMODEL; k0 += 16) {
        fillA_plain(A, DMODEL, m0, k0, As, tid);
        fillB_n(B, 3*DMODEL, k0, n0, Bs, tid);
        __syncthreads();
        warp_mma_stage(As, Bs, mrow, ncol, kq, c);
        __syncthreads();
    }
    int reg = blockIdx.x >> 2;
    float* dst = (reg == 0) ? g_q : ((reg == 1) ? g_k : g_v);
    #pragma unroll
    for (int mt = 0; mt < 2; mt++) {
        int r0 = m0 + wm*32 + mt*16 + (lane>>2);
        #pragma unroll
        for (int nt = 0; nt < 8; nt++) {
            int gcol = n0 + wn*64 + nt*8 + 2*kq;
            float2 bv = *(const float2*)(bias + gcol);
            int col = gcol - reg*512;
            *(float2*)(dst + (size_t)r0*DMODEL + col) =
                make_float2(c[mt][nt][0] + bv.x, c[mt][nt][1] + bv.y);
            *(float2*)(dst + (size_t)(r0+8)*DMODEL + col) =
                make_float2(c[mt][nt][2] + bv.x, c[mt][nt][3] + bv.y);
        }
    }
}

// ---------------- K5a: zero ctx ----------------
__global__ void zero_ctx_kernel() {
    int i = blockIdx.x * blockDim.x + threadIdx.x;
    ((float4*)g_ctx)[i] = make_float4(0.f, 0.f, 0.f, 0.f);
}

// ---------------- K3: FLASH attention (fused QK^T + online softmax + PV) ----------------
// grid (4 d-chunks, 8 t-tiles, 32 zb), 256 threads = 8 warps along m (16 rows each).
struct SmemFlash {
    union {
        float2 As[16][PAD];      // Q split tile (S phase)
        float  Ps[32][PADH];     // P tile [s][t] (PV phase)
    };
    float2 Bs[16][PAD];          // K split (S) / V split (PV)
    unsigned char kms[TT];       // padding mask row
};

__global__ __launch_bounds__(256) void flash_kernel(const unsigned char* __restrict__ kpm) {
    __shared__ SmemFlash smf;
    int z = blockIdx.z; int h = z >> 2; int b = z & 3;
    int dlo = g_dlo[h], dhi = g_dhi[h];
    int dbase = dlo & ~15;
    int d0 = dbase + blockIdx.x * 128;
    if (d0 >= dhi) return;
    int klo = dlo & ~15;
    int khi = (dhi + 15) & ~15;
    int t0 = blockIdx.y * 128;
    const float* Q = g_q + (size_t)b*TT*DMODEL;
    const float* K = g_k + (size_t)b*TT*DMODEL;
    const float* V = g_v + (size_t)b*TT*DMODEL;
    const float* m2 = g_m2 + h*DMODEL;
    const float* mskv = g_maskv + h*DMODEL;
    float isc = g_inv_scale[h];

    int tid = threadIdx.x, lane = tid & 31, wid = tid >> 5;
    int wrow = wid*16 + (lane >> 2);    // this thread's row (t-local); +8 = second row
    int kq = lane & 3;
    int ncol = lane >> 2;

    // preload padding mask row
    ((uint32_t*)smf.kms)[tid] = ((const uint32_t*)(kpm + b*TT))[tid];

    float m0r = -INFINITY, m1r = -INFINITY;
    float l0r = 0.0f, l1r = 0.0f;
    float o[16][4] = {};

    for (int s0 = 0; s0 < TT; s0 += 32) {
        // ---- S phase: c[4][4] = (Q*m2) @ K^T over window ----
        float c[4][4] = {};
        for (int k0 = klo; k0 < khi; k0 += 16) {
            __syncthreads();   // prior phase consumers done (PV mma read Ps/Bs)
            fillA_scaled(Q, DMODEL, t0, k0, m2, smf.As, tid);
            fillB_k32(K, k0, s0, smf.Bs, tid);
            __syncthreads();
            #pragma unroll
            for (int k8o = 0; k8o < 16; k8o += 8) {
                uint32_t ah[4], al[4];
                float2 x0 = smf.As[k8o+kq  ][wrow];
                float2 x1 = smf.As[k8o+kq  ][wrow+8];
                float2 x2 = smf.As[k8o+4+kq][wrow];
                float2 x3 = smf.As[k8o+4+kq][wrow+8];
                ah[0]=__float_as_uint(x0.x); al[0]=__float_as_uint(x0.y);
                ah[1]=__float_as_uint(x1.x); al[1]=__float_as_uint(x1.y);
                ah[2]=__float_as_uint(x2.x); al[2]=__float_as_uint(x2.y);
                ah[3]=__float_as_uint(x3.x); al[3]=__float_as_uint(x3.y);
                #pragma unroll
                for (int nt = 0; nt < 4; nt++) {
                    float2 y0 = smf.Bs[k8o+kq  ][ncol + nt*8];
                    float2 y1 = smf.Bs[k8o+4+kq][ncol + nt*8];
                    uint32_t bh0=__float_as_uint(y0.x), bl0=__float_as_uint(y0.y);
                    uint32_t bh1=__float_as_uint(y1.x), bl1=__float_as_uint(y1.y);
                    mma8(c[nt], ah, bh0, bh1);
                    mma8(c[nt], ah, bl0, bl1);
                    mma8(c[nt], al, bh0, bh1);
                }
            }
        }
        __syncthreads();   // all warps done reading As before Ps overwrite

        // ---- online softmax (warp-local rows) ----
        float mt0 = -INFINITY, mt1 = -INFINITY;
        #pragma unroll
        for (int nt = 0; nt < 4; nt++) {
            int sc = s0 + nt*8 + 2*kq;
            bool km0 = smf.kms[sc], km1 = smf.kms[sc+1];
            float v0 = km0 ? NEG_INF_F : c[nt][0]*isc;
            float v1 = km1 ? NEG_INF_F : c[nt][1]*isc;
            float v2 = km0 ? NEG_INF_F : c[nt][2]*isc;
            float v3 = km1 ? NEG_INF_F : c[nt][3]*isc;
            c[nt][0]=v0; c[nt][1]=v1; c[nt][2]=v2; c[nt][3]=v3;
            mt0 = fmaxf(mt0, fmaxf(v0, v1));
            mt1 = fmaxf(mt1, fmaxf(v2, v3));
        }
        mt0 = fmaxf(mt0, __shfl_xor_sync(0xffffffffu, mt0, 1));
        mt0 = fmaxf(mt0, __shfl_xor_sync(0xffffffffu, mt0, 2));
        mt1 = fmaxf(mt1, __shfl_xor_sync(0xffffffffu, mt1, 1));
        mt1 = fmaxf(mt1, __shfl_xor_sync(0xffffffffu, mt1, 2));
        float mn0 = fmaxf(m0r, mt0), mn1 = fmaxf(m1r, mt1);
        float sc0 = __expf(m0r - mn0), sc1 = __expf(m1r - mn1);
        m0r = mn0; m1r = mn1;
        float ps0 = 0.0f, ps1 = 0.0f;
        #pragma unroll
        for (int nt = 0; nt < 4; nt++) {
            int cl = nt*8 + 2*kq;
            float p0 = __expf(c[nt][0] - mn0);
            float p1 = __expf(c[nt][1] - mn0);
            float p2 = __expf(c[nt][2] - mn1);
            float p3 = __expf(c[nt][3] - mn1);
            ps0 += p0 + p1; ps1 += p2 + p3;
            smf.Ps[cl  ][wrow]   = tf32_rna(p0);
            smf.Ps[cl+1][wrow]   = tf32_rna(p1);
            smf.Ps[cl  ][wrow+8] = tf32_rna(p2);
            smf.Ps[cl+1][wrow+8] = tf32_rna(p3);
        }
        ps0 += __shfl_xor_sync(0xffffffffu, ps0, 1);
        ps0 += __shfl_xor_sync(0xffffffffu, ps0, 2);
        ps1 += __shfl_xor_sync(0xffffffffu, ps1, 1);
        ps1 += __shfl_xor_sync(0xffffffffu, ps1, 2);
        l0r = l0r*sc0 + ps0;
        l1r = l1r*sc1 + ps1;
        #pragma unroll
        for (int nt = 0; nt < 16; nt++) {
            o[nt][0] *= sc0; o[nt][1] *= sc0;
            o[nt][2] *= sc1; o[nt][3] *= sc1;
        }

        // ---- PV phase: o += P @ V (k = 32 s, n = 128 d) ----
        #pragma unroll
        for (int st = 0; st < 2; st++) {
            __syncthreads();   // S mma / prior PV done reading Bs
            fillB_nV(V, s0 + st*16, d0, smf.Bs, tid);
            __syncthreads();
            #pragma unroll
            for (int k8o = 0; k8o < 16; k8o += 8) {
                uint32_t ah[4];
                ah[0] = __float_as_uint(smf.Ps[st*16+k8o+kq  ][wrow]);
                ah[1] = __float_as_uint(smf.Ps[st*16+k8o+kq  ][wrow+8]);
                ah[2] = __float_as_uint(smf.Ps[st*16+k8o+4+kq][wrow]);
                ah[3] = __float_as_uint(smf.Ps[st*16+k8o+4+kq][wrow+8]);
                #pragma unroll
                for (int nt = 0; nt < 16; nt++) {
                    float2 y0 = smf.Bs[k8o+kq  ][ncol + nt*8];
                    float2 y1 = smf.Bs[k8o+4+kq][ncol + nt*8];
                    uint32_t bh0=__float_as_uint(y0.x), bl0=__float_as_uint(y0.y);
                    uint32_t bh1=__float_as_uint(y1.x), bl1=__float_as_uint(y1.y);
                    mma8(o[nt], ah, bh0, bh1);
                    mma8(o[nt], ah, bl0, bl1);
                }
            }
        }
    }

    // ---- epilogue: scale by 1/l, mask, atomic accumulate over window ----
    float inv0 = 1.0f / l0r, inv1 = 1.0f / l1r;
    int tg0 = t0 + wrow;
    #pragma unroll
    for (int nt = 0; nt < 16; nt++) {
        int d = d0 + nt*8 + 2*kq;
        bool in0 = (d >= dlo) && (d < dhi);
        bool in1 = (d+1 >= dlo) && (d+1 < dhi);
        float* base0 = &g_ctx[(size_t)b*TT*DMODEL + (size_t)tg0*DMODEL + d];
        float* base1 = base0 + 8*DMODEL;
        if (in0) {
            float mk = mskv[d];
            atomicAdd(base0,     o[nt][0] * mk * inv0);
            atomicAdd(base1,     o[nt][2] * mk * inv1);
        }
        if (in1) {
            float mk = mskv[d+1];
            atomicAdd(base0 + 1, o[nt][1] * mk * inv0);
            atomicAdd(base1 + 1, o[nt][3] * mk * inv1);
        }
    }
}

// ---------------- K6: out = ctx @ Wout + bout + query ----------------
__global__ __launch_bounds__(256) void mma_out(const float* __restrict__ B,
                                               const float* __restrict__ bias,
                                               const float* __restrict__ resid) {
    __shared__ float2 As[16][PAD], Bs[16][PAD];
    int tid = threadIdx.x, lane = tid & 31, wid = tid >> 5;
    int wm = wid >> 1, wn = wid & 1;
    int m0 = blockIdx.y * 128, n0 = blockIdx.x * 128;
    int mrow = wm*32 + (lane>>2), ncol = wn*64 + (lane>>2), kq = lane & 3;
    float c[2][8][4] = {};
    for (int k0 = 0; k0 < DMODEL; k0 += 16) {
        fillA_plain(g_ctx, DMODEL, m0, k0, As, tid);
        fillB_n(B, DMODEL, k0, n0, Bs, tid);
        __syncthreads();
        warp_mma_stage(As, Bs, mrow, ncol, kq, c);
        __syncthreads();
    }
    #pragma unroll
    for (int mt = 0; mt < 2; mt++) {
        int r0 = m0 + wm*32 + mt*16 + (lane>>2);
        #pragma unroll
        for (int nt = 0; nt < 8; nt++) {
            int col = n0 + wn*64 + nt*8 + 2*kq;
            float2 bv = *(const float2*)(bias + col);
            float2 q0 = *(const float2*)(resid + (size_t)r0*DMODEL + col);
            float2 q1 = *(const float2*)(resid + (size_t)(r0+8)*DMODEL + col);
            *(float2*)(g_res + (size_t)r0*DMODEL + col) =
                make_float2(c[mt][nt][0] + bv.x + q0.x, c[mt][nt][1] + bv.y + q0.y);
            *(float2*)(g_res + (size_t)(r0+8)*DMODEL + col) =
                make_float2(c[mt][nt][2] + bv.x + q1.x, c[mt][nt][3] + bv.y + q1.y);
        }
    }
}

// ---------------- block reduce (LN) ----------------
__device__ __forceinline__ float block_reduce_sum(float v) {
    __shared__ float sh[32];
    __syncthreads();
    int lane = threadIdx.x & 31, wid = threadIdx.x >> 5;
    #pragma unroll
    for (int o = 16; o > 0; o >>= 1) v += __shfl_xor_sync(0xffffffffu, v, o);
    if (lane == 0) sh[wid] = v;
    __syncthreads();
    if (wid == 0) {
        int nw = blockDim.x >> 5;
        v = (lane < nw) ? sh[lane] : 0.0f;
        #pragma unroll
        for (int o = 16; o > 0; o >>= 1) v += __shfl_xor_sync(0xffffffffu, v, o);
        if (lane == 0) sh[0] = v;
    }
    __syncthreads();
    return sh[0];
}

// ---------------- K1: head params / masks / windows ----------------
__global__ void head_params_kernel(const float* __restrict__ hw) {
    __shared__ float dims[HH], starts[HH];
    int tid = threadIdx.x;
    if (tid == 0) {
        float mx = -1e30f;
        for (int h = 0; h < HH; h++) mx = fmaxf(mx, hw[h]);
        float e[HH]; float s = 0.0f;
        for (int h = 0; h < HH; h++) { e[h] = expf(hw[h] - mx); s += e[h]; }
        float run = 0.0f;
        const float adj = (float)(DMODEL - 16*HH);   // 384
        for (int h = 0; h < HH; h++) {
            float gg = e[h] / s;
            float dd = fmaxf(16.0f + gg * adj, 0.0f);
            dims[h] = dd; starts[h] = run;
            g_inv_scale[h] = rsqrtf(dd + 1e-6f);
            int lo = (int)floorf(run - 2.5f);        if (lo < 0) lo = 0;
            int hi = (int)ceilf(run + dd + 2.5f);    if (hi > DMODEL) hi = DMODEL;
            g_dlo[h] = lo; g_dhi[h] = hi;
            run += dd;
        }
    }
    __syncthreads();
    float p = (float)tid;   // tid in [0,512)
    for (int h = 0; h < HH; h++) {
        float l = 1.0f / (1.0f + expf(-(p - starts[h]) * 10.0f));
        float r = 1.0f / (1.0f + expf(-(starts[h] + dims[h] - p) * 10.0f));
        float m = l * r;
        g_maskv[h*DMODEL + tid] = m;
        g_m2[h*DMODEL + tid]   = m * m;
    }
}

// ---------------- K7: LayerNorm -> d_out ----------------
__global__ __launch_bounds__(256) void ln_kernel(const float* __restrict__ gamma,
                                                 const float* __restrict__ beta,
                                                 float* __restrict__ out) {
    int row = blockIdx.x;
    int tid = threadIdx.x;
    float2 v = ((const float2*)(g_res + (size_t)row*DMODEL))[tid];
    float s = block_reduce_sum(v.x + v.y);
    float mu = s * (1.0f / DMODEL);
    float d0 = v.x - mu, d1 = v.y - mu;
    float sq = block_reduce_sum(d0*d0 + d1*d1);
    float var = sq * (1.0f / DMODEL);
    float r = rsqrtf(var + 1e-5f);
    float2 g  = ((const float2*)gamma)[tid];
    float2 bt = ((const float2*)beta)[tid];
    float2 o;
    o.x = d0 * r * g.x + bt.x;
    o.y = d1 * r * g.y + bt.y;
    ((float2*)(out + (size_t)row*DMODEL))[tid] = o;
}

// ---------------- launch ----------------
extern "C" void kernel_launch(void* const* d_in, const int* in_sizes, int n_in,
                              void* d_out, int out_size) {
    const float* query = (const float*)d_in[0];
    const float* hw    = (const float*)d_in[1];
    const float* Wqkv  = (const float*)d_in[2];
    const float* bqkv  = (const float*)d_in[3];
    const float* Wout  = (const float*)d_in[4];
    const float* bout  = (const float*)d_in[5];
    const float* gamma = (const float*)d_in[6];
    const float* beta  = (const float*)d_in[7];
    const unsigned char* kpm = (const unsigned char*)d_in[8];
    float* out = (float*)d_out;

    head_params_kernel<<<1, DMODEL>>>(hw);
    mma_qkv<<<dim3(3*DMODEL/128, BB*TT/128), 256>>>(query, Wqkv, bqkv);
    zero_ctx_kernel<<<(BB*TT*DMODEL/4)/256, 256>>>();
    flash_kernel<<<dim3(4, TT/128, HH*BB), 256>>>(kpm);
    mma_out<<<dim3(DMODEL/128, BB*TT/128), 256>>>(Wout, bout, query);
    ln_kernel<<<BB*TT, 256>>>(gamma, beta, out);
}

// round 13
// speedup vs baseline: 2.3832x; 2.3832x over previous
#include <cuda_runtime.h>
#include <cstdint>
#include <math.h>

#define BB 4
#define TT 1024
#define DMODEL 512
#define HH 8
#define NEG_INF_F (-1000000000.0f)
#define NROWS (HH*BB*TT)   // 32768 softmax rows
#define NSTAT 16           // per-row stat slots (64-col granularity)

// ---------------- scratch (device globals; no allocation) ----------------
__device__ float g_q[BB*TT*DMODEL];
__device__ float g_k[BB*TT*DMODEL];
__device__ float g_v[BB*TT*DMODEL];
__device__ float g_res[BB*TT*DMODEL];
__device__ float g_scores[(size_t)HH*BB*TT*TT];   // stores exp(S - m_tile)
__device__ float g_smax[(size_t)NROWS*NSTAT];
__device__ float g_ssum[(size_t)NROWS*NSTAT];
__device__ float g_mrow[NROWS];
__device__ float g_linv[NROWS];
__device__ float g_maskv[HH*DMODEL];
__device__ float g_m2[HH*DMODEL];
__device__ float g_inv_scale[HH];
__device__ int   g_dlo[HH];
__device__ int   g_dhi[HH];
__device__ float g_ctx[BB*TT*DMODEL];

// ================= mma.sync tf32 machinery =================
__device__ __forceinline__ float tf32_rna(float x) {
    float r; asm("cvt.rna.tf32.f32 %0, %1;" : "=f"(r) : "f"(x)); return r;
}
__device__ __forceinline__ float2 split_tf32(float x) {
    float h = tf32_rna(x);
    return make_float2(h, x - h);
}
__device__ __forceinline__ void mma8(float c[4], const uint32_t a[4], uint32_t b0, uint32_t b1) {
    asm volatile(
        "mma.sync.aligned.m16n8k8.row.col.f32.tf32.tf32.f32 "
        "{%0,%1,%2,%3}, {%4,%5,%6,%7}, {%8,%9}, {%0,%1,%2,%3};"
        : "+f"(c[0]), "+f"(c[1]), "+f"(c[2]), "+f"(c[3])
        : "r"(a[0]), "r"(a[1]), "r"(a[2]), "r"(a[3]), "r"(b0), "r"(b1));
}

#define PAD 133    // float2 per k-row (split tiles)
#define PADH 136   // float per k-row (hi-only P tile)

// 3-term stage (qkv/scores/out): 4m x 2n warp layout
__device__ __forceinline__ void warp_mma_stage(const float2 (*As)[PAD], const float2 (*Bs)[PAD],
                                               int mrow, int ncol, int kq, float c[2][8][4]) {
    #pragma unroll
    for (int k8o = 0; k8o < 16; k8o += 8) {
        uint32_t ah[2][4], al[2][4];
        #pragma unroll
        for (int mt = 0; mt < 2; mt++) {
            float2 x0 = As[k8o+kq  ][mrow + mt*16];
            float2 x1 = As[k8o+kq  ][mrow + mt*16 + 8];
            float2 x2 = As[k8o+4+kq][mrow + mt*16];
            float2 x3 = As[k8o+4+kq][mrow + mt*16 + 8];
            ah[mt][0] = __float_as_uint(x0.x); al[mt][0] = __float_as_uint(x0.y);
            ah[mt][1] = __float_as_uint(x1.x); al[mt][1] = __float_as_uint(x1.y);
            ah[mt][2] = __float_as_uint(x2.x); al[mt][2] = __float_as_uint(x2.y);
            ah[mt][3] = __float_as_uint(x3.x); al[mt][3] = __float_as_uint(x3.y);
        }
        #pragma unroll
        for (int nt = 0; nt < 8; nt++) {
            float2 y0 = Bs[k8o+kq  ][ncol + nt*8];
            float2 y1 = Bs[k8o+4+kq][ncol + nt*8];
            uint32_t bh0 = __float_as_uint(y0.x), bl0 = __float_as_uint(y0.y);
            uint32_t bh1 = __float_as_uint(y1.x), bl1 = __float_as_uint(y1.y);
            #pragma unroll
            for (int mt = 0; mt < 2; mt++) {
                mma8(c[mt][nt], ah[mt], bh0, bh1);
                mma8(c[mt][nt], ah[mt], bl0, bl1);
                mma8(c[mt][nt], al[mt], bh0, bh1);
            }
        }
    }
}

// 2-term PV stage (A = P hi-only, B = V split)
__device__ __forceinline__ void warp_mma_stage_pv(const float (*Ah)[PADH], const float2 (*Bs)[PAD],
                                                  int mrow, int ncol, int kq, float c[2][8][4]) {
    #pragma unroll
    for (int k8o = 0; k8o < 16; k8o += 8) {
        uint32_t ah[2][4];
        #pragma unroll
        for (int mt = 0; mt < 2; mt++) {
            ah[mt][0] = __float_as_uint(Ah[k8o+kq  ][mrow + mt*16]);
            ah[mt][1] = __float_as_uint(Ah[k8o+kq  ][mrow + mt*16 + 8]);
            ah[mt][2] = __float_as_uint(Ah[k8o+4+kq][mrow + mt*16]);
            ah[mt][3] = __float_as_uint(Ah[k8o+4+kq][mrow + mt*16 + 8]);
        }
        #pragma unroll
        for (int nt = 0; nt < 8; nt++) {
            float2 y0 = Bs[k8o+kq  ][ncol + nt*8];
            float2 y1 = Bs[k8o+4+kq][ncol + nt*8];
            uint32_t bh0 = __float_as_uint(y0.x), bl0 = __float_as_uint(y0.y);
            uint32_t bh1 = __float_as_uint(y1.x), bl1 = __float_as_uint(y1.y);
            #pragma unroll
            for (int mt = 0; mt < 2; mt++) {
                mma8(c[mt][nt], ah[mt], bh0, bh1);
                mma8(c[mt][nt], ah[mt], bl0, bl1);
            }
        }
    }
}

// ---------------- K2: QKV projection (4096x1536x512), reg-prefetch ----------------
__global__ __launch_bounds__(256, 2) void mma_qkv(const float* __restrict__ A,
                                                  const float* __restrict__ B,
                                                  const float* __restrict__ bias) {
    __shared__ float2 As[16][PAD], Bs[16][PAD];
    int tid = threadIdx.x, lane = tid & 31, wid = tid >> 5;
    int wm = wid >> 1, wn = wid & 1;
    int m0 = blockIdx.y * 128, n0 = blockIdx.x * 128;
    int mrow = wm*32 + (lane>>2), ncol = wn*64 + (lane>>2), kq = lane & 3;
    int am = tid >> 2, ak = (tid & 3) << 2;      // A: rows am, am+64; cols ak..ak+3
    int bk = tid >> 5, bn = (tid & 31) << 2;     // B: k-rows bk, bk+8; cols bn..bn+3
    const float* Ar0 = A + (size_t)(m0+am)*DMODEL + ak;
    const float* Ar1 = A + (size_t)(m0+am+64)*DMODEL + ak;
    float4 pa0 = *(const float4*)Ar0;
    float4 pa1 = *(const float4*)Ar1;
    float4 pb0 = *(const float4*)(B + (size_t)bk*(3*DMODEL) + n0 + bn);
    float4 pb1 = *(const float4*)(B + (size_t)(bk+8)*(3*DMODEL) + n0 + bn);
    float c[2][8][4] = {};
    for (int k0 = 0; k0 < DMODEL; k0 += 16) {
        As[ak+0][am] = split_tf32(pa0.x); As[ak+1][am] = split_tf32(pa0.y);
        As[ak+2][am] = split_tf32(pa0.z); As[ak+3][am] = split_tf32(pa0.w);
        As[ak+0][am+64] = split_tf32(pa1.x); As[ak+1][am+64] = split_tf32(pa1.y);
        As[ak+2][am+64] = split_tf32(pa1.z); As[ak+3][am+64] = split_tf32(pa1.w);
        Bs[bk  ][bn+0] = split_tf32(pb0.x); Bs[bk  ][bn+1] = split_tf32(pb0.y);
        Bs[bk  ][bn+2] = split_tf32(pb0.z); Bs[bk  ][bn+3] = split_tf32(pb0.w);
        Bs[bk+8][bn+0] = split_tf32(pb1.x); Bs[bk+8][bn+1] = split_tf32(pb1.y);
        Bs[bk+8][bn+2] = split_tf32(pb1.z); Bs[bk+8][bn+3] = split_tf32(pb1.w);
        __syncthreads();
        int kn = k0 + 16;
        if (kn < DMODEL) {
            pa0 = *(const float4*)(Ar0 + kn);
            pa1 = *(const float4*)(Ar1 + kn);
            pb0 = *(const float4*)(B + (size_t)(kn+bk)*(3*DMODEL) + n0 + bn);
            pb1 = *(const float4*)(B + (size_t)(kn+bk+8)*(3*DMODEL) + n0 + bn);
        }
        warp_mma_stage(As, Bs, mrow, ncol, kq, c);
        __syncthreads();
    }
    int reg = blockIdx.x >> 2;
    float* dst = (reg == 0) ? g_q : ((reg == 1) ? g_k : g_v);
    #pragma unroll
    for (int mt = 0; mt < 2; mt++) {
        int r0 = m0 + wm*32 + mt*16 + (lane>>2);
        #pragma unroll
        for (int nt = 0; nt < 8; nt++) {
            int gcol = n0 + wn*64 + nt*8 + 2*kq;
            float2 bv = *(const float2*)(bias + gcol);
            int col = gcol - reg*512;
            *(float2*)(dst + (size_t)r0*DMODEL + col) =
                make_float2(c[mt][nt][0] + bv.x, c[mt][nt][1] + bv.y);
            *(float2*)(dst + (size_t)(r0+8)*DMODEL + col) =
                make_float2(c[mt][nt][2] + bv.x, c[mt][nt][3] + bv.y);
        }
    }
}

// ---------------- K3: scores -> exp(S - m_tile), stats per 64-col tile ----------------
__global__ __launch_bounds__(256, 2) void mma_scores(const unsigned char* __restrict__ kpm) {
    __shared__ float2 As[16][PAD], Bs[16][PAD];
    int z = blockIdx.z; int h = z >> 2; int b = z & 3;
    int lo = g_dlo[h] & ~15;
    int hi = (g_dhi[h] + 15) & ~15;
    const float* Q  = g_q + (size_t)b*TT*DMODEL;
    const float* Kp = g_k + (size_t)b*TT*DMODEL;
    const float* m2 = g_m2 + h*DMODEL;
    int tid = threadIdx.x, lane = tid & 31, wid = tid >> 5;
    int wm = wid >> 1, wn = wid & 1;
    int t0 = blockIdx.y * 128, s0 = blockIdx.x * 128;
    int mrow = wm*32 + (lane>>2), ncol = wn*64 + (lane>>2), kq = lane & 3;
    int am = tid >> 2, ak = (tid & 3) << 2;
    const float* Qr0 = Q  + (size_t)(t0+am)*DMODEL + ak;
    const float* Qr1 = Q  + (size_t)(t0+am+64)*DMODEL + ak;
    const float* Kr0 = Kp + (size_t)(s0+am)*DMODEL + ak;
    const float* Kr1 = Kp + (size_t)(s0+am+64)*DMODEL + ak;
    const float* M2p = m2 + ak;
    float4 pq0 = *(const float4*)(Qr0 + lo);
    float4 pq1 = *(const float4*)(Qr1 + lo);
    float4 pk0 = *(const float4*)(Kr0 + lo);
    float4 pk1 = *(const float4*)(Kr1 + lo);
    float4 pm  = *(const float4*)(M2p + lo);
    float c[2][8][4] = {};
    for (int k0 = lo; k0 < hi; k0 += 16) {
        As[ak+0][am] = split_tf32(pq0.x*pm.x); As[ak+1][am] = split_tf32(pq0.y*pm.y);
        As[ak+2][am] = split_tf32(pq0.z*pm.z); As[ak+3][am] = split_tf32(pq0.w*pm.w);
        As[ak+0][am+64] = split_tf32(pq1.x*pm.x); As[ak+1][am+64] = split_tf32(pq1.y*pm.y);
        As[ak+2][am+64] = split_tf32(pq1.z*pm.z); As[ak+3][am+64] = split_tf32(pq1.w*pm.w);
        Bs[ak+0][am] = split_tf32(pk0.x); Bs[ak+1][am] = split_tf32(pk0.y);
        Bs[ak+2][am] = split_tf32(pk0.z); Bs[ak+3][am] = split_tf32(pk0.w);
        Bs[ak+0][am+64] = split_tf32(pk1.x); Bs[ak+1][am+64] = split_tf32(pk1.y);
        Bs[ak+2][am+64] = split_tf32(pk1.z); Bs[ak+3][am+64] = split_tf32(pk1.w);
        __syncthreads();
        int kn = k0 + 16;
        if (kn < hi) {
            pq0 = *(const float4*)(Qr0 + kn);
            pq1 = *(const float4*)(Qr1 + kn);
            pk0 = *(const float4*)(Kr0 + kn);
            pk1 = *(const float4*)(Kr1 + kn);
            pm  = *(const float4*)(M2p + kn);
        }
        warp_mma_stage(As, Bs, mrow, ncol, kq, c);
        __syncthreads();
    }
    float isc = g_inv_scale[h];
    float* Sout = g_scores + (size_t)z*TT*TT;
    float km0[8], km1[8];
    #pragma unroll
    for (int nt = 0; nt < 8; nt++) {
        int sc = s0 + wn*64 + nt*8 + 2*kq;
        km0[nt] = kpm[b*TT + sc]     ? 1.0f : 0.0f;
        km1[nt] = kpm[b*TT + sc + 1] ? 1.0f : 0.0f;
    }
    int stile = blockIdx.x*2 + wn;
    #pragma unroll
    for (int mt = 0; mt < 2; mt++) {
        #pragma unroll
        for (int half = 0; half < 2; half++) {
            int t = t0 + wm*32 + mt*16 + (lane>>2) + half*8;
            float vv0[8], vv1[8];
            float mr = -INFINITY;
            #pragma unroll
            for (int nt = 0; nt < 8; nt++) {
                float x0 = c[mt][nt][half*2+0] * isc;
                float x1 = c[mt][nt][half*2+1] * isc;
                x0 = (km0[nt] != 0.0f) ? NEG_INF_F : x0;
                x1 = (km1[nt] != 0.0f) ? NEG_INF_F : x1;
                vv0[nt] = x0; vv1[nt] = x1;
                mr = fmaxf(mr, fmaxf(x0, x1));
            }
            mr = fmaxf(mr, __shfl_xor_sync(0xffffffffu, mr, 1));
            mr = fmaxf(mr, __shfl_xor_sync(0xffffffffu, mr, 2));
            float l = 0.0f;
            #pragma unroll
            for (int nt = 0; nt < 8; nt++) {
                float e0 = __expf(vv0[nt] - mr);
                float e1 = __expf(vv1[nt] - mr);
                vv0[nt] = e0; vv1[nt] = e1;
                l += e0 + e1;
            }
            l += __shfl_xor_sync(0xffffffffu, l, 1);
            l += __shfl_xor_sync(0xffffffffu, l, 2);
            if (kq == 0) {
                size_t ridx = ((size_t)z*TT + t)*NSTAT + stile;
                g_smax[ridx] = mr;
                g_ssum[ridx] = l;
            }
            #pragma unroll
            for (int nt = 0; nt < 8; nt++) {
                int sc = s0 + wn*64 + nt*8 + 2*kq;
                *(float2*)(Sout + (size_t)t*TT + sc) = make_float2(vv0[nt], vv1[nt]);
            }
        }
    }
}

// ---------------- K4: combine per-tile stats -> (m, 1/l) per row ----------------
__global__ __launch_bounds__(256) void combine_kernel() {
    int r = blockIdx.x * 256 + threadIdx.x;
    if (r >= NROWS) return;
    float mm = -INFINITY;
    float m[NSTAT], l[NSTAT];
    #pragma unroll
    for (int k = 0; k < NSTAT; k++) {
        m[k] = g_smax[(size_t)r*NSTAT + k];
        l[k] = g_ssum[(size_t)r*NSTAT + k];
        mm = fmaxf(mm, m[k]);
    }
    float ll = 0.0f;
    #pragma unroll
    for (int k = 0; k < NSTAT; k++) ll += l[k] * __expf(m[k] - mm);
    g_mrow[r] = mm;
    g_linv[r] = 1.0f / ll;
}

// ---------------- K5a: zero ctx ----------------
__global__ void zero_ctx_kernel() {
    int i = blockIdx.x * blockDim.x + threadIdx.x;
    ((float4*)g_ctx)[i] = make_float4(0.f, 0.f, 0.f, 0.f);
}

// ---------------- K5: ctx += P @ (v*mask); P from stored exp * corr table ----------------
__global__ __launch_bounds__(256, 2) void mma_ctx() {
    __shared__ float  Ah[16][PADH];
    __shared__ float2 Bs[16][PAD];
    __shared__ float  corr[128][NSTAT+1];
    int z = blockIdx.z; int h = z >> 2; int b = z & 3;
    int dlo = g_dlo[h], dhi = g_dhi[h];
    int d0 = blockIdx.x * 128;
    if (d0 >= dhi || d0 + 128 <= dlo) return;
    const float* S   = g_scores + (size_t)z*TT*TT;
    const float* V   = g_v + (size_t)b*TT*DMODEL;
    const float* msk = g_maskv + h*DMODEL;
    int tid = threadIdx.x, lane = tid & 31, wid = tid >> 5;
    int wm = wid >> 1, wn = wid & 1;
    int t0 = blockIdx.y * 128;
    int zrow = z*TT + t0;
    int mrow = wm*32 + (lane>>2), ncol = wn*64 + (lane>>2), kq = lane & 3;
    int am = tid >> 2, ak = (tid & 3) << 2;
    int bk = tid >> 5, bn = (tid & 31) << 2;
    // build corr table: corr[row][tile] = exp(m_tile - m_row) * linv_row
    #pragma unroll
    for (int i = 0; i < 8; i++) {
        int idx = tid*8 + i;
        int row = idx >> 4, tile = idx & 15;
        float mr = g_mrow[zrow + row];
        float li = g_linv[zrow + row];
        float mt = g_smax[(size_t)(zrow + row)*NSTAT + tile];
        corr[row][tile] = __expf(mt - mr) * li;
    }
    __syncthreads();
    const float* Sr0 = S + (size_t)(t0+am)*TT + ak;
    const float* Sr1 = S + (size_t)(t0+am+64)*TT + ak;
    float4 ps0 = *(const float4*)Sr0;
    float4 ps1 = *(const float4*)Sr1;
    float4 pv0 = *(const float4*)(V + (size_t)bk*DMODEL + d0 + bn);
    float4 pv1 = *(const float4*)(V + (size_t)(bk+8)*DMODEL + d0 + bn);
    float c[2][8][4] = {};
    for (int k0 = 0; k0 < TT; k0 += 16) {
        float cr0 = corr[am   ][(k0 + ak) >> 6];
        float cr1 = corr[am+64][(k0 + ak) >> 6];
        Ah[ak+0][am] = tf32_rna(ps0.x * cr0); Ah[ak+1][am] = tf32_rna(ps0.y * cr0);
        Ah[ak+2][am] = tf32_rna(ps0.z * cr0); Ah[ak+3][am] = tf32_rna(ps0.w * cr0);
        Ah[ak+0][am+64] = tf32_rna(ps1.x * cr1); Ah[ak+1][am+64] = tf32_rna(ps1.y * cr1);
        Ah[ak+2][am+64] = tf32_rna(ps1.z * cr1); Ah[ak+3][am+64] = tf32_rna(ps1.w * cr1);
        Bs[bk  ][bn+0] = split_tf32(pv0.x); Bs[bk  ][bn+1] = split_tf32(pv0.y);
        Bs[bk  ][bn+2] = split_tf32(pv0.z); Bs[bk  ][bn+3] = split_tf32(pv0.w);
        Bs[bk+8][bn+0] = split_tf32(pv1.x); Bs[bk+8][bn+1] = split_tf32(pv1.y);
        Bs[bk+8][bn+2] = split_tf32(pv1.z); Bs[bk+8][bn+3] = split_tf32(pv1.w);
        __syncthreads();
        int kn = k0 + 16;
        if (kn < TT) {
            ps0 = *(const float4*)(Sr0 + kn);
            ps1 = *(const float4*)(Sr1 + kn);
            pv0 = *(const float4*)(V + (size_t)(kn+bk)*DMODEL + d0 + bn);
            pv1 = *(const float4*)(V + (size_t)(kn+bk+8)*DMODEL + d0 + bn);
        }
        warp_mma_stage_pv(Ah, Bs, mrow, ncol, kq, c);
        __syncthreads();
    }
    #pragma unroll
    for (int nt = 0; nt < 8; nt++) {
        int d = d0 + wn*64 + nt*8 + 2*kq;
        float mk0 = msk[d], mk1 = msk[d+1];
        bool in0 = (d >= dlo) && (d < dhi);
        bool in1 = (d+1 >= dlo) && (d+1 < dhi);
        #pragma unroll
        for (int mt = 0; mt < 2; mt++) {
            int r0 = t0 + wm*32 + mt*16 + (lane>>2);
            float* base0 = &g_ctx[(size_t)b*TT*DMODEL + (size_t)r0*DMODEL + d];
            float* base1 = base0 + 8*DMODEL;
            if (in0) {
                atomicAdd(base0,     c[mt][nt][0] * mk0);
                atomicAdd(base1,     c[mt][nt][2] * mk0);
            }
            if (in1) {
                atomicAdd(base0 + 1, c[mt][nt][1] * mk1);
                atomicAdd(base1 + 1, c[mt][nt][3] * mk1);
            }
        }
    }
}

// ---------------- K6: out = ctx @ Wout + bout + query ----------------
__global__ __launch_bounds__(256, 2) void mma_out(const float* __restrict__ B,
                                                  const float* __restrict__ bias,
                                                  const float* __restrict__ resid) {
    __shared__ float2 As[16][PAD], Bs[16][PAD];
    int tid = threadIdx.x, lane = tid & 31, wid = tid >> 5;
    int wm = wid >> 1, wn = wid & 1;
    int m0 = blockIdx.y * 128, n0 = blockIdx.x * 128;
    int mrow = wm*32 + (lane>>2), ncol = wn*64 + (lane>>2), kq = lane & 3;
    int am = tid >> 2, ak = (tid & 3) << 2;
    int bk = tid >> 5, bn = (tid & 31) << 2;
    const float* Ar0 = g_ctx + (size_t)(m0+am)*DMODEL + ak;
    const float* Ar1 = g_ctx + (size_t)(m0+am+64)*DMODEL + ak;
    float4 pa0 = *(const float4*)Ar0;
    float4 pa1 = *(const float4*)Ar1;
    float4 pb0 = *(const float4*)(B + (size_t)bk*DMODEL + n0 + bn);
    float4 pb1 = *(const float4*)(B + (size_t)(bk+8)*DMODEL + n0 + bn);
    float c[2][8][4] = {};
    for (int k0 = 0; k0 < DMODEL; k0 += 16) {
        As[ak+0][am] = split_tf32(pa0.x); As[ak+1][am] = split_tf32(pa0.y);
        As[ak+2][am] = split_tf32(pa0.z); As[ak+3][am] = split_tf32(pa0.w);
        As[ak+0][am+64] = split_tf32(pa1.x); As[ak+1][am+64] = split_tf32(pa1.y);
        As[ak+2][am+64] = split_tf32(pa1.z); As[ak+3][am+64] = split_tf32(pa1.w);
        Bs[bk  ][bn+0] = split_tf32(pb0.x); Bs[bk  ][bn+1] = split_tf32(pb0.y);
        Bs[bk  ][bn+2] = split_tf32(pb0.z); Bs[bk  ][bn+3] = split_tf32(pb0.w);
        Bs[bk+8][bn+0] = split_tf32(pb1.x); Bs[bk+8][bn+1] = split_tf32(pb1.y);
        Bs[bk+8][bn+2] = split_tf32(pb1.z); Bs[bk+8][bn+3] = split_tf32(pb1.w);
        __syncthreads();
        int kn = k0 + 16;
        if (kn < DMODEL) {
            pa0 = *(const float4*)(Ar0 + kn);
            pa1 = *(const float4*)(Ar1 + kn);
            pb0 = *(const float4*)(B + (size_t)(kn+bk)*DMODEL + n0 + bn);
            pb1 = *(const float4*)(B + (size_t)(kn+bk+8)*DMODEL + n0 + bn);
        }
        warp_mma_stage(As, Bs, mrow, ncol, kq, c);
        __syncthreads();
    }
    #pragma unroll
    for (int mt = 0; mt < 2; mt++) {
        int r0 = m0 + wm*32 + mt*16 + (lane>>2);
        #pragma unroll
        for (int nt = 0; nt < 8; nt++) {
            int col = n0 + wn*64 + nt*8 + 2*kq;
            float2 bv = *(const float2*)(bias + col);
            float2 q0 = *(const float2*)(resid + (size_t)r0*DMODEL + col);
            float2 q1 = *(const float2*)(resid + (size_t)(r0+8)*DMODEL + col);
            *(float2*)(g_res + (size_t)r0*DMODEL + col) =
                make_float2(c[mt][nt][0] + bv.x + q0.x, c[mt][nt][1] + bv.y + q0.y);
            *(float2*)(g_res + (size_t)(r0+8)*DMODEL + col) =
                make_float2(c[mt][nt][2] + bv.x + q1.x, c[mt][nt][3] + bv.y + q1.y);
        }
    }
}

// ---------------- block reduce (LN) ----------------
__device__ __forceinline__ float block_reduce_sum(float v) {
    __shared__ float sh[32];
    __syncthreads();
    int lane = threadIdx.x & 31, wid = threadIdx.x >> 5;
    #pragma unroll
    for (int o = 16; o > 0; o >>= 1) v += __shfl_xor_sync(0xffffffffu, v, o);
    if (lane == 0) sh[wid] = v;
    __syncthreads();
    if (wid == 0) {
        int nw = blockDim.x >> 5;
        v = (lane < nw) ? sh[lane] : 0.0f;
        #pragma unroll
        for (int o = 16; o > 0; o >>= 1) v += __shfl_xor_sync(0xffffffffu, v, o);
        if (lane == 0) sh[0] = v;
    }
    __syncthreads();
    return sh[0];
}

// ---------------- K1: head params / masks / windows ----------------
__global__ void head_params_kernel(const float* __restrict__ hw) {
    __shared__ float dims[HH], starts[HH];
    int tid = threadIdx.x;
    if (tid == 0) {
        float mx = -1e30f;
        for (int h = 0; h < HH; h++) mx = fmaxf(mx, hw[h]);
        float e[HH]; float s = 0.0f;
        for (int h = 0; h < HH; h++) { e[h] = expf(hw[h] - mx); s += e[h]; }
        float run = 0.0f;
        const float adj = (float)(DMODEL - 16*HH);   // 384
        for (int h = 0; h < HH; h++) {
            float gg = e[h] / s;
            float dd = fmaxf(16.0f + gg * adj, 0.0f);
            dims[h] = dd; starts[h] = run;
            g_inv_scale[h] = rsqrtf(dd + 1e-6f);
            int lo = (int)floorf(run - 2.5f);        if (lo < 0) lo = 0;
            int hi = (int)ceilf(run + dd + 2.5f);    if (hi > DMODEL) hi = DMODEL;
            g_dlo[h] = lo; g_dhi[h] = hi;
            run += dd;
        }
    }
    __syncthreads();
    float p = (float)tid;   // tid in [0,512)
    for (int h = 0; h < HH; h++) {
        float l = 1.0f / (1.0f + expf(-(p - starts[h]) * 10.0f));
        float r = 1.0f / (1.0f + expf(-(starts[h] + dims[h] - p) * 10.0f));
        float m = l * r;
        g_maskv[h*DMODEL + tid] = m;
        g_m2[h*DMODEL + tid]   = m * m;
    }
}

// ---------------- K7: LayerNorm -> d_out ----------------
__global__ __launch_bounds__(256) void ln_kernel(const float* __restrict__ gamma,
                                                 const float* __restrict__ beta,
                                                 float* __restrict__ out) {
    int row = blockIdx.x;
    int tid = threadIdx.x;
    float2 v = ((const float2*)(g_res + (size_t)row*DMODEL))[tid];
    float s = block_reduce_sum(v.x + v.y);
    float mu = s * (1.0f / DMODEL);
    float d0 = v.x - mu, d1 = v.y - mu;
    float sq = block_reduce_sum(d0*d0 + d1*d1);
    float var = sq * (1.0f / DMODEL);
    float r = rsqrtf(var + 1e-5f);
    float2 g  = ((const float2*)gamma)[tid];
    float2 bt = ((const float2*)beta)[tid];
    float2 o;
    o.x = d0 * r * g.x + bt.x;
    o.y = d1 * r * g.y + bt.y;
    ((float2*)(out + (size_t)row*DMODEL))[tid] = o;
}

// ---------------- launch ----------------
extern "C" void kernel_launch(void* const* d_in, const int* in_sizes, int n_in,
                              void* d_out, int out_size) {
    const float* query = (const float*)d_in[0];
    const float* hw    = (const float*)d_in[1];
    const float* Wqkv  = (const float*)d_in[2];
    const float* bqkv  = (const float*)d_in[3];
    const float* Wout  = (const float*)d_in[4];
    const float* bout  = (const float*)d_in[5];
    const float* gamma = (const float*)d_in[6];
    const float* beta  = (const float*)d_in[7];
    const unsigned char* kpm = (const unsigned char*)d_in[8];
    float* out = (float*)d_out;

    head_params_kernel<<<1, DMODEL>>>(hw);
    mma_qkv<<<dim3(3*DMODEL/128, BB*TT/128), 256>>>(query, Wqkv, bqkv);
    zero_ctx_kernel<<<(BB*TT*DMODEL/4)/256, 256>>>();
    mma_scores<<<dim3(TT/128, TT/128, HH*BB), 256>>>(kpm);
    combine_kernel<<<NROWS/256, 256>>>();
    mma_ctx<<<dim3(DMODEL/128, TT/128, HH*BB), 256>>>();
    mma_out<<<dim3(DMODEL/128, BB*TT/128), 256>>>(Wout, bout, query);
    ln_kernel<<<BB*TT, 256>>>(gamma, beta, out);
}

// round 16
// speedup vs baseline: 3.7405x; 1.5695x over previous
#include <cuda_runtime.h>
#include <cstdint>
#include <math.h>

#define BB 4
#define TT 1024
#define DMODEL 512
#define HH 8
#define NEG_INF_F (-1000000000.0f)
#define NROWS (HH*BB*TT)   // 32768 softmax rows
#define NSTAT 16           // per-row stat slots (64-col granularity)

// ---------------- scratch (device globals; no allocation) ----------------
__device__ float g_q[BB*TT*DMODEL];
__device__ float g_k[BB*TT*DMODEL];
__device__ float g_v[BB*TT*DMODEL];
__device__ float g_res[BB*TT*DMODEL];
__device__ float g_scores[(size_t)HH*BB*TT*TT];   // stores exp(S - m_tile)
__device__ float g_smax[(size_t)NROWS*NSTAT];
__device__ float g_ssum[(size_t)NROWS*NSTAT];
__device__ float g_mrow[NROWS];
__device__ float g_linv[NROWS];
__device__ float g_maskv[HH*DMODEL];
__device__ float g_m2[HH*DMODEL];
__device__ float g_inv_scale[HH];
__device__ int   g_dlo[HH];
__device__ int   g_dhi[HH];
__device__ float g_ctx[BB*TT*DMODEL];

// ================= bf16 m16n8k16 mma machinery =================
#define PADB 136   // u32 per kpair row; 136 % 32 == 8 -> conflict-free fragment loads

__device__ __forceinline__ void mma16(float c[4], const uint32_t a[4], uint32_t b0, uint32_t b1) {
    asm volatile(
        "mma.sync.aligned.m16n8k16.row.col.f32.bf16.bf16.f32 "
        "{%0,%1,%2,%3}, {%4,%5,%6,%7}, {%8,%9}, {%0,%1,%2,%3};"
        : "+f"(c[0]), "+f"(c[1]), "+f"(c[2]), "+f"(c[3])
        : "r"(a[0]), "r"(a[1]), "r"(a[2]), "r"(a[3]), "r"(b0), "r"(b1));
}
// pack truncated-bf16 of (a,b): result low half = trunc(a), high = trunc(b)
__device__ __forceinline__ uint32_t prmt_hi(float a, float b) {
    uint32_t r;
    asm("prmt.b32 %0, %1, %2, 0x7632;" : "=r"(r)
        : "r"(__float_as_uint(a)), "r"(__float_as_uint(b)));
    return r;
}
__device__ __forceinline__ float trunc_bf(float x) {
    return __uint_as_float(__float_as_uint(x) & 0xFFFF0000u);
}
// pack rn-bf16 of (even,odd): low half = even
__device__ __forceinline__ uint32_t pack_rn(float e, float o) {
    uint32_t r;
    asm("cvt.rn.bf16x2.f32 %0, %1, %2;" : "=r"(r) : "f"(o), "f"(e));
    return r;
}
__device__ __forceinline__ void split4(float4 v, uint32_t& h01, uint32_t& h23,
                                       uint32_t& l01, uint32_t& l23) {
    h01 = prmt_hi(v.x, v.y);
    h23 = prmt_hi(v.z, v.w);
    l01 = pack_rn(v.x - trunc_bf(v.x), v.y - trunc_bf(v.y));
    l23 = pack_rn(v.z - trunc_bf(v.z), v.w - trunc_bf(v.w));
}

// fill along-k: src row-major [m][k](ld); rows r0+m, r0+m+64; 4 k's -> 2 kpairs
__device__ __forceinline__ void fill_mk(const float* __restrict__ src, int ld, int r0, int k0,
                                        uint32_t (*H)[PADB], uint32_t (*L)[PADB], int tid) {
    int m = tid >> 2, kp = (tid & 3) << 1;
    #pragma unroll
    for (int half = 0; half < 2; half++) {
        int mm = m + half*64;
        float4 v = *(const float4*)(src + (size_t)(r0+mm)*ld + k0 + kp*2);
        uint32_t h01,h23,l01,l23; split4(v,h01,h23,l01,l23);
        H[kp][mm]=h01; H[kp+1][mm]=h23; L[kp][mm]=l01; L[kp+1][mm]=l23;
    }
}
// B row-major [k][n](ld): pack along k (2-row reads), vectorized STS.128
__device__ __forceinline__ void fill_kn(const float* __restrict__ src, int ld, int k0, int n0,
                                        uint32_t (*H)[PADB], uint32_t (*L)[PADB], int tid) {
    int kp = tid >> 5, n4 = (tid & 31) << 2;
    const float* p = src + (size_t)(k0 + kp*2)*ld + n0 + n4;
    float4 v0 = *(const float4*)p;
    float4 v1 = *(const float4*)(p + ld);
    uint4 h, l;
    h.x = prmt_hi(v0.x, v1.x); h.y = prmt_hi(v0.y, v1.y);
    h.z = prmt_hi(v0.z, v1.z); h.w = prmt_hi(v0.w, v1.w);
    l.x = pack_rn(v0.x - trunc_bf(v0.x), v1.x - trunc_bf(v1.x));
    l.y = pack_rn(v0.y - trunc_bf(v0.y), v1.y - trunc_bf(v1.y));
    l.z = pack_rn(v0.z - trunc_bf(v0.z), v1.z - trunc_bf(v1.z));
    l.w = pack_rn(v0.w - trunc_bf(v0.w), v1.w - trunc_bf(v1.w));
    *(uint4*)&H[kp][n4] = h;
    *(uint4*)&L[kp][n4] = l;
}

// 3-term 16-k stage: c[2 mtiles][8 ntiles][4]
__device__ __forceinline__ void stage3(const uint32_t (*Ahi)[PADB], const uint32_t (*Alo)[PADB],
                                       const uint32_t (*Bhi)[PADB], const uint32_t (*Blo)[PADB],
                                       int mrow, int ncol, int t, float c[2][8][4]) {
    uint32_t ah[2][4], al[2][4];
    #pragma unroll
    for (int mt = 0; mt < 2; mt++) {
        int r = mrow + mt*16;
        ah[mt][0]=Ahi[t][r]; ah[mt][1]=Ahi[t][r+8]; ah[mt][2]=Ahi[t+4][r]; ah[mt][3]=Ahi[t+4][r+8];
        al[mt][0]=Alo[t][r]; al[mt][1]=Alo[t][r+8]; al[mt][2]=Alo[t+4][r]; al[mt][3]=Alo[t+4][r+8];
    }
    #pragma unroll
    for (int nt = 0; nt < 8; nt++) {
        int cl = ncol + nt*8;
        uint32_t bh0=Bhi[t][cl], bh1=Bhi[t+4][cl];
        uint32_t bl0=Blo[t][cl], bl1=Blo[t+4][cl];
        #pragma unroll
        for (int mt = 0; mt < 2; mt++) {
            mma16(c[mt][nt], ah[mt], bh0, bh1);
            mma16(c[mt][nt], ah[mt], bl0, bl1);
            mma16(c[mt][nt], al[mt], bh0, bh1);
        }
    }
}

// ---------------- K2: QKV projection (4096x1536x512) ----------------
__global__ __launch_bounds__(256, 2) void mma_qkv(const float* __restrict__ A,
                                                  const float* __restrict__ B,
                                                  const float* __restrict__ bias) {
    __shared__ uint32_t Ah[8][PADB], Al[8][PADB], Bh[8][PADB], Bl[8][PADB];
    int tid = threadIdx.x, lane = tid & 31, wid = tid >> 5;
    int wm = wid >> 1, wn = wid & 1;
    int m0 = blockIdx.y * 128, n0 = blockIdx.x * 128;
    int mrow = wm*32 + (lane>>2), ncol = wn*64 + (lane>>2), t = lane & 3;
    float c[2][8][4] = {};
    for (int k0 = 0; k0 < DMODEL; k0 += 16) {
        fill_mk(A, DMODEL, m0, k0, Ah, Al, tid);
        fill_kn(B, 3*DMODEL, k0, n0, Bh, Bl, tid);
        __syncthreads();
        stage3(Ah, Al, Bh, Bl, mrow, ncol, t, c);
        __syncthreads();
    }
    int reg = blockIdx.x >> 2;
    float* dst = (reg == 0) ? g_q : ((reg == 1) ? g_k : g_v);
    #pragma unroll
    for (int mt = 0; mt < 2; mt++) {
        int r0 = m0 + wm*32 + mt*16 + (lane>>2);
        #pragma unroll
        for (int nt = 0; nt < 8; nt++) {
            int gcol = n0 + wn*64 + nt*8 + 2*t;
            float2 bv = *(const float2*)(bias + gcol);
            int col = gcol - reg*512;
            *(float2*)(dst + (size_t)r0*DMODEL + col) =
                make_float2(c[mt][nt][0] + bv.x, c[mt][nt][1] + bv.y);
            *(float2*)(dst + (size_t)(r0+8)*DMODEL + col) =
                make_float2(c[mt][nt][2] + bv.x, c[mt][nt][3] + bv.y);
        }
    }
}

// ---------------- K3: scores -> exp(S - m_tile), stats per 64-col tile ----------------
__global__ __launch_bounds__(256, 2) void mma_scores(const unsigned char* __restrict__ kpm) {
    __shared__ uint32_t Ah[8][PADB], Al[8][PADB], Bh[8][PADB], Bl[8][PADB];
    int z = blockIdx.z; int h = z >> 2; int b = z & 3;
    int lo = g_dlo[h] & ~15;
    int hi = (g_dhi[h] + 15) & ~15;
    const float* Q  = g_q + (size_t)b*TT*DMODEL;
    const float* Kp = g_k + (size_t)b*TT*DMODEL;
    const float* m2 = g_m2 + h*DMODEL;
    int tid = threadIdx.x, lane = tid & 31, wid = tid >> 5;
    int wm = wid >> 1, wn = wid & 1;
    int t0 = blockIdx.y * 128, s0 = blockIdx.x * 128;
    int mrow = wm*32 + (lane>>2), ncol = wn*64 + (lane>>2), t = lane & 3;
    int am = tid >> 2, kp = (tid & 3) << 1;
    float c[2][8][4] = {};
    for (int k0 = lo; k0 < hi; k0 += 16) {
        // A = Q * m2 (rows am, am+64), split
        float4 s = *(const float4*)(m2 + k0 + kp*2);
        #pragma unroll
        for (int half = 0; half < 2; half++) {
            int mm = am + half*64;
            float4 v = *(const float4*)(Q + (size_t)(t0+mm)*DMODEL + k0 + kp*2);
            v.x *= s.x; v.y *= s.y; v.z *= s.z; v.w *= s.w;
            uint32_t h01,h23,l01,l23; split4(v,h01,h23,l01,l23);
            Ah[kp][mm]=h01; Ah[kp+1][mm]=h23; Al[kp][mm]=l01; Al[kp+1][mm]=l23;
        }
        // B = K rows (s-major), k along dk — same fill shape as A
        fill_mk(Kp, DMODEL, s0, k0, Bh, Bl, tid);
        __syncthreads();
        stage3(Ah, Al, Bh, Bl, mrow, ncol, t, c);
        __syncthreads();
    }
    float isc = g_inv_scale[h];
    float* Sout = g_scores + (size_t)z*TT*TT;
    float km0[8], km1[8];
    #pragma unroll
    for (int nt = 0; nt < 8; nt++) {
        int sc = s0 + wn*64 + nt*8 + 2*t;
        km0[nt] = kpm[b*TT + sc]     ? 1.0f : 0.0f;
        km1[nt] = kpm[b*TT + sc + 1] ? 1.0f : 0.0f;
    }
    int stile = blockIdx.x*2 + wn;
    #pragma unroll
    for (int mt = 0; mt < 2; mt++) {
        #pragma unroll
        for (int half = 0; half < 2; half++) {
            int tr = t0 + wm*32 + mt*16 + (lane>>2) + half*8;
            float vv0[8], vv1[8];
            float mr = -INFINITY;
            #pragma unroll
            for (int nt = 0; nt < 8; nt++) {
                float x0 = c[mt][nt][half*2+0] * isc;
                float x1 = c[mt][nt][half*2+1] * isc;
                x0 = (km0[nt] != 0.0f) ? NEG_INF_F : x0;
                x1 = (km1[nt] != 0.0f) ? NEG_INF_F : x1;
                vv0[nt] = x0; vv1[nt] = x1;
                mr = fmaxf(mr, fmaxf(x0, x1));
            }
            mr = fmaxf(mr, __shfl_xor_sync(0xffffffffu, mr, 1));
            mr = fmaxf(mr, __shfl_xor_sync(0xffffffffu, mr, 2));
            float l = 0.0f;
            #pragma unroll
            for (int nt = 0; nt < 8; nt++) {
                float e0 = __expf(vv0[nt] - mr);
                float e1 = __expf(vv1[nt] - mr);
                vv0[nt] = e0; vv1[nt] = e1;
                l += e0 + e1;
            }
            l += __shfl_xor_sync(0xffffffffu, l, 1);
            l += __shfl_xor_sync(0xffffffffu, l, 2);
            if (t == 0) {
                size_t ridx = ((size_t)z*TT + tr)*NSTAT + stile;
                g_smax[ridx] = mr;
                g_ssum[ridx] = l;
            }
            #pragma unroll
            for (int nt = 0; nt < 8; nt++) {
                int sc = s0 + wn*64 + nt*8 + 2*t;
                *(float2*)(Sout + (size_t)tr*TT + sc) = make_float2(vv0[nt], vv1[nt]);
            }
        }
    }
}

// ---------------- K4: combine per-tile stats -> (m, 1/l) per row ----------------
__global__ __launch_bounds__(256) void combine_kernel() {
    int r = blockIdx.x * 256 + threadIdx.x;
    if (r >= NROWS) return;
    float mm = -INFINITY;
    float m[NSTAT], l[NSTAT];
    #pragma unroll
    for (int k = 0; k < NSTAT; k++) {
        m[k] = g_smax[(size_t)r*NSTAT + k];
        l[k] = g_ssum[(size_t)r*NSTAT + k];
        mm = fmaxf(mm, m[k]);
    }
    float ll = 0.0f;
    #pragma unroll
    for (int k = 0; k < NSTAT; k++) ll += l[k] * __expf(m[k] - mm);
    g_mrow[r] = mm;
    g_linv[r] = 1.0f / ll;
}

// ---------------- K5a: zero ctx ----------------
__global__ void zero_ctx_kernel() {
    int i = blockIdx.x * blockDim.x + threadIdx.x;
    ((float4*)g_ctx)[i] = make_float4(0.f, 0.f, 0.f, 0.f);
}

// ---------------- K5: ctx += P @ (v*mask); P from stored exp * corr table ----------------
__global__ __launch_bounds__(256, 2) void mma_ctx() {
    __shared__ uint32_t Ah[8][PADB], Al[8][PADB], Bh[8][PADB], Bl[8][PADB];
    __shared__ float corr[128][NSTAT+1];
    int z = blockIdx.z; int h = z >> 2; int b = z & 3;
    int dlo = g_dlo[h], dhi = g_dhi[h];
    int d0 = blockIdx.x * 128;
    if (d0 >= dhi || d0 + 128 <= dlo) return;
    const float* S   = g_scores + (size_t)z*TT*TT;
    const float* V   = g_v + (size_t)b*TT*DMODEL;
    const float* msk = g_maskv + h*DMODEL;
    int tid = threadIdx.x, lane = tid & 31, wid = tid >> 5;
    int wm = wid >> 1, wn = wid & 1;
    int t0 = blockIdx.y * 128;
    int zrow = z*TT + t0;
    int mrow = wm*32 + (lane>>2), ncol = wn*64 + (lane>>2), t = lane & 3;
    int am = tid >> 2, kp = (tid & 3) << 1;
    #pragma unroll
    for (int i = 0; i < 8; i++) {
        int idx = tid*8 + i;
        int row = idx >> 4, tile = idx & 15;
        float mr = g_mrow[zrow + row];
        float li = g_linv[zrow + row];
        float mt = g_smax[(size_t)(zrow + row)*NSTAT + tile];
        corr[row][tile] = __expf(mt - mr) * li;
    }
    __syncthreads();
    float c[2][8][4] = {};
    for (int k0 = 0; k0 < TT; k0 += 16) {
        #pragma unroll
        for (int half = 0; half < 2; half++) {
            int mm = am + half*64;
            float cr = corr[mm][(k0 + kp*2) >> 6];
            float4 v = *(const float4*)(S + (size_t)(t0+mm)*TT + k0 + kp*2);
            v.x *= cr; v.y *= cr; v.z *= cr; v.w *= cr;
            uint32_t h01,h23,l01,l23; split4(v,h01,h23,l01,l23);
            Ah[kp][mm]=h01; Ah[kp+1][mm]=h23; Al[kp][mm]=l01; Al[kp+1][mm]=l23;
        }
        fill_kn(V, DMODEL, k0, d0, Bh, Bl, tid);
        __syncthreads();
        stage3(Ah, Al, Bh, Bl, mrow, ncol, t, c);
        __syncthreads();
    }
    #pragma unroll
    for (int nt = 0; nt < 8; nt++) {
        int d = d0 + wn*64 + nt*8 + 2*t;
        float mk0 = msk[d], mk1 = msk[d+1];
        bool in0 = (d >= dlo) && (d < dhi);
        bool in1 = (d+1 >= dlo) && (d+1 < dhi);
        #pragma unroll
        for (int mt = 0; mt < 2; mt++) {
            int r0 = t0 + wm*32 + mt*16 + (lane>>2);
            float* base0 = &g_ctx[(size_t)b*TT*DMODEL + (size_t)r0*DMODEL + d];
            float* base1 = base0 + 8*DMODEL;
            if (in0) {
                atomicAdd(base0,     c[mt][nt][0] * mk0);
                atomicAdd(base1,     c[mt][nt][2] * mk0);
            }
            if (in1) {
                atomicAdd(base0 + 1, c[mt][nt][1] * mk1);
                atomicAdd(base1 + 1, c[mt][nt][3] * mk1);
            }
        }
    }
}

// ---------------- K6: out = ctx @ Wout + bout + query ----------------
__global__ __launch_bounds__(256, 2) void mma_out(const float* __restrict__ B,
                                                  const float* __restrict__ bias,
                                                  const float* __restrict__ resid) {
    __shared__ uint32_t Ah[8][PADB], Al[8][PADB], Bh[8][PADB], Bl[8][PADB];
    int tid = threadIdx.x, lane = tid & 31, wid = tid >> 5;
    int wm = wid >> 1, wn = wid & 1;
    int m0 = blockIdx.y * 128, n0 = blockIdx.x * 128;
    int mrow = wm*32 + (lane>>2), ncol = wn*64 + (lane>>2), t = lane & 3;
    float c[2][8][4] = {};
    for (int k0 = 0; k0 < DMODEL; k0 += 16) {
        fill_mk(g_ctx, DMODEL, m0, k0, Ah, Al, tid);
        fill_kn(B, DMODEL, k0, n0, Bh, Bl, tid);
        __syncthreads();
        stage3(Ah, Al, Bh, Bl, mrow, ncol, t, c);
        __syncthreads();
    }
    #pragma unroll
    for (int mt = 0; mt < 2; mt++) {
        int r0 = m0 + wm*32 + mt*16 + (lane>>2);
        #pragma unroll
        for (int nt = 0; nt < 8; nt++) {
            int col = n0 + wn*64 + nt*8 + 2*t;
            float2 bv = *(const float2*)(bias + col);
            float2 q0 = *(const float2*)(resid + (size_t)r0*DMODEL + col);
            float2 q1 = *(const float2*)(resid + (size_t)(r0+8)*DMODEL + col);
            *(float2*)(g_res + (size_t)r0*DMODEL + col) =
                make_float2(c[mt][nt][0] + bv.x + q0.x, c[mt][nt][1] + bv.y + q0.y);
            *(float2*)(g_res + (size_t)(r0+8)*DMODEL + col) =
                make_float2(c[mt][nt][2] + bv.x + q1.x, c[mt][nt][3] + bv.y + q1.y);
        }
    }
}

// ---------------- block reduce (LN) ----------------
__device__ __forceinline__ float block_reduce_sum(float v) {
    __shared__ float sh[32];
    __syncthreads();
    int lane = threadIdx.x & 31, wid = threadIdx.x >> 5;
    #pragma unroll
    for (int o = 16; o > 0; o >>= 1) v += __shfl_xor_sync(0xffffffffu, v, o);
    if (lane == 0) sh[wid] = v;
    __syncthreads();
    if (wid == 0) {
        int nw = blockDim.x >> 5;
        v = (lane < nw) ? sh[lane] : 0.0f;
        #pragma unroll
        for (int o = 16; o > 0; o >>= 1) v += __shfl_xor_sync(0xffffffffu, v, o);
        if (lane == 0) sh[0] = v;
    }
    __syncthreads();
    return sh[0];
}

// ---------------- K1: head params / masks / windows ----------------
__global__ void head_params_kernel(const float* __restrict__ hw) {
    __shared__ float dims[HH], starts[HH];
    int tid = threadIdx.x;
    if (tid == 0) {
        float mx = -1e30f;
        for (int h = 0; h < HH; h++) mx = fmaxf(mx, hw[h]);
        float e[HH]; float s = 0.0f;
        for (int h = 0; h < HH; h++) { e[h] = expf(hw[h] - mx); s += e[h]; }
        float run = 0.0f;
        const float adj = (float)(DMODEL - 16*HH);   // 384
        for (int h = 0; h < HH; h++) {
            float gg = e[h] / s;
            float dd = fmaxf(16.0f + gg * adj, 0.0f);
            dims[h] = dd; starts[h] = run;
            g_inv_scale[h] = rsqrtf(dd + 1e-6f);
            int lo = (int)floorf(run - 2.5f);        if (lo < 0) lo = 0;
            int hi = (int)ceilf(run + dd + 2.5f);    if (hi > DMODEL) hi = DMODEL;
            g_dlo[h] = lo; g_dhi[h] = hi;
            run += dd;
        }
    }
    __syncthreads();
    float p = (float)tid;   // tid in [0,512)
    for (int h = 0; h < HH; h++) {
        float l = 1.0f / (1.0f + expf(-(p - starts[h]) * 10.0f));
        float r = 1.0f / (1.0f + expf(-(starts[h] + dims[h] - p) * 10.0f));
        float m = l * r;
        g_maskv[h*DMODEL + tid] = m;
        g_m2[h*DMODEL + tid]   = m * m;
    }
}

// ---------------- K7: LayerNorm -> d_out ----------------
__global__ __launch_bounds__(256) void ln_kernel(const float* __restrict__ gamma,
                                                 const float* __restrict__ beta,
                                                 float* __restrict__ out) {
    int row = blockIdx.x;
    int tid = threadIdx.x;
    float2 v = ((const float2*)(g_res + (size_t)row*DMODEL))[tid];
    float s = block_reduce_sum(v.x + v.y);
    float mu = s * (1.0f / DMODEL);
    float d0 = v.x - mu, d1 = v.y - mu;
    float sq = block_reduce_sum(d0*d0 + d1*d1);
    float var = sq * (1.0f / DMODEL);
    float r = rsqrtf(var + 1e-5f);
    float2 g  = ((const float2*)gamma)[tid];
    float2 bt = ((const float2*)beta)[tid];
    float2 o;
    o.x = d0 * r * g.x + bt.x;
    o.y = d1 * r * g.y + bt.y;
    ((float2*)(out + (size_t)row*DMODEL))[tid] = o;
}

// ---------------- launch ----------------
extern "C" void kernel_launch(void* const* d_in, const int* in_sizes, int n_in,
                              void* d_out, int out_size) {
    const float* query = (const float*)d_in[0];
    const float* hw    = (const float*)d_in[1];
    const float* Wqkv  = (const float*)d_in[2];
    const float* bqkv  = (const float*)d_in[3];
    const float* Wout  = (const float*)d_in[4];
    const float* bout  = (const float*)d_in[5];
    const float* gamma = (const float*)d_in[6];
    const float* beta  = (const float*)d_in[7];
    const unsigned char* kpm = (const unsigned char*)d_in[8];
    float* out = (float*)d_out;

    head_params_kernel<<<1, DMODEL>>>(hw);
    mma_qkv<<<dim3(3*DMODEL/128, BB*TT/128), 256>>>(query, Wqkv, bqkv);
    zero_ctx_kernel<<<(BB*TT*DMODEL/4)/256, 256>>>();
    mma_scores<<<dim3(TT/128, TT/128, HH*BB), 256>>>(kpm);
    combine_kernel<<<NROWS/256, 256>>>();
    mma_ctx<<<dim3(DMODEL/128, TT/128, HH*BB), 256>>>();
    mma_out<<<dim3(DMODEL/128, BB*TT/128), 256>>>(Wout, bout, query);
    ln_kernel<<<BB*TT, 256>>>(gamma, beta, out);
}